// round 2
// baseline (speedup 1.0000x reference)
#include <cuda_runtime.h>
#include <cstdint>

// HMM forward filter:
//   pred0 = init @ T
//   for k: est = L1norm(pred * lik[:,k,:]); pred = est @ T
// Shapes: lik [B=256, H=2048, S=64], init [64], T [64,64] row-major.
// Outputs: est_traj [B,H,S] then pred_traj [B,H,S] concatenated in d_out.
//
// Layout: block = 128 threads = 2 batches (64 threads each).
//   batch-local thread bt in [0,64): p = bt&31 (state pair: states p and p+32),
//   q = bt>>5 (i-half of the matvec: i in [32q, 32q+32)).
//   Each thread holds packed T columns TT[ii] = {T[i][p], T[i][p+32]} in regs.
//   est is broadcast through shared mem as duplicated pairs {e_i, e_i} so the
//   matvec inner loop is LDS.128(broadcast) + fma.rn.f32x2.
//   L1 sum: both warps of a batch hold all 32 pairs redundantly -> pure
//   warp-shuffle butterfly, no barrier. Exactly 2 __syncthreads per step.

#define Bn 256
#define Hn 2048
#define Sn 64
#define HMM_EPS 1e-12f

using u64 = unsigned long long;

__device__ __forceinline__ u64 fma2(u64 a, u64 b, u64 c) {
    u64 d; asm("fma.rn.f32x2 %0, %1, %2, %3;" : "=l"(d) : "l"(a), "l"(b), "l"(c)); return d;
}
__device__ __forceinline__ u64 mul2(u64 a, u64 b) {
    u64 d; asm("mul.rn.f32x2 %0, %1, %2;" : "=l"(d) : "l"(a), "l"(b)); return d;
}
__device__ __forceinline__ u64 add2(u64 a, u64 b) {
    u64 d; asm("add.rn.f32x2 %0, %1, %2;" : "=l"(d) : "l"(a), "l"(b)); return d;
}
__device__ __forceinline__ u64 pack2(float lo, float hi) {
    u64 d; asm("mov.b64 %0, {%1, %2};" : "=l"(d) : "f"(lo), "f"(hi)); return d;
}
__device__ __forceinline__ void unpack2(u64 a, float& x, float& y) {
    asm("mov.b64 {%0, %1}, %2;" : "=f"(x), "=f"(y) : "l"(a));
}
__device__ __forceinline__ float fast_rcp(float s) {
    float r; asm("rcp.approx.f32 %0, %1;" : "=f"(r) : "f"(s)); return r;
}

__global__ void __launch_bounds__(128) hmm_forward_kernel(
    const float* __restrict__ lik,    // [B, H, S]
    const float* __restrict__ init_s, // [S]
    const float* __restrict__ Tm,     // [S, S] row-major
    float* __restrict__ est_out,      // [B, H, S]
    float* __restrict__ pred_out)     // [B, H, S]
{
    __shared__ alignas(16) u64 est_dup[2][Sn];     // {e_i, e_i} per state, per local batch
    __shared__ alignas(16) u64 part[2][32][2];     // partial matvec sums [batch][pair][q]

    const int tid = threadIdx.x;
    const int lb  = tid >> 6;        // local batch 0/1
    const int bt  = tid & 63;
    const int p   = bt & 31;         // state pair: states p, p+32
    const int q   = bt >> 5;         // i-half: [32q, 32q+32)
    const int b   = blockIdx.x * 2 + lb;

    // ---- load T columns into registers, packed {T[i][p], T[i][p+32]} ----
    u64 TT[32];
#pragma unroll
    for (int ii = 0; ii < 32; ii++) {
        const int i = q * 32 + ii;
        TT[ii] = pack2(Tm[i * Sn + p], Tm[i * Sn + p + 32]);
    }

    const float* likp = lik + (size_t)b * Hn * Sn;
    float* eo = est_out + (size_t)b * Hn * Sn;
    float* po = pred_out + (size_t)b * Hn * Sn;

    // first lik values (prefetched)
    float l0 = likp[p];
    float l1 = likp[p + 32];

    // ---- pred0 = init @ T : stage init into est_dup and run one matvec ----
    if (q == 0) {
        float a = init_s[p];
        float c = init_s[p + 32];
        est_dup[lb][p]      = pack2(a, a);
        est_dup[lb][p + 32] = pack2(c, c);
    }
    __syncthreads();

    u64 pred2;
    {
        const ulonglong2* ev = reinterpret_cast<const ulonglong2*>(&est_dup[lb][q * 32]);
        u64 a0 = 0, a1 = 0, a2 = 0, a3 = 0;
#pragma unroll
        for (int t = 0; t < 16; t += 2) {
            ulonglong2 v0 = ev[t];
            ulonglong2 v1 = ev[t + 1];
            a0 = fma2(v0.x, TT[2 * t + 0], a0);
            a1 = fma2(v0.y, TT[2 * t + 1], a1);
            a2 = fma2(v1.x, TT[2 * t + 2], a2);
            a3 = fma2(v1.y, TT[2 * t + 3], a3);
        }
        part[lb][p][q] = add2(add2(a0, a1), add2(a2, a3));
    }
    __syncthreads();
    {
        ulonglong2 pr = *reinterpret_cast<const ulonglong2*>(&part[lb][p][0]);
        pred2 = add2(pr.x, pr.y);
    }

    // ---- main recurrence ----
    for (int k = 0; k < Hn; k++) {
        // u = pred * lik_k
        u64 u2 = mul2(pred2, pack2(l0, l1));
        float ux, uy; unpack2(u2, ux, uy);

        // s = sum |u| over all 64 states (each warp holds all 32 pairs)
        float s = fabsf(ux) + fabsf(uy);
#pragma unroll
        for (int o = 16; o; o >>= 1) s += __shfl_xor_sync(0xFFFFFFFFu, s, o);
        s = fmaxf(s, HMM_EPS);
        const float r = fast_rcp(s);

        u64 e2 = mul2(u2, pack2(r, r));
        float ex, ey; unpack2(e2, ex, ey);

        if (q == 0) {
            est_dup[lb][p] = pack2(ex, ex);
            eo[k * Sn + p]      = ex;     // est output (2 coalesced 128B stores/warp)
            eo[k * Sn + p + 32] = ey;
        } else {
            est_dup[lb][p + 32] = pack2(ey, ey);
        }
        __syncthreads();   // BAR1: est_dup visible; prev-step part reads done

        // prefetch next step's lik while matvec runs
        const int kn = (k + 1 < Hn) ? (k + 1) : k;
        const float n0 = likp[kn * Sn + p];
        const float n1 = likp[kn * Sn + p + 32];

        // matvec partial over this thread's i-half
        {
            const ulonglong2* ev = reinterpret_cast<const ulonglong2*>(&est_dup[lb][q * 32]);
            u64 a0 = 0, a1 = 0, a2 = 0, a3 = 0;
#pragma unroll
            for (int t = 0; t < 16; t += 2) {
                ulonglong2 v0 = ev[t];
                ulonglong2 v1 = ev[t + 1];
                a0 = fma2(v0.x, TT[2 * t + 0], a0);
                a1 = fma2(v0.y, TT[2 * t + 1], a1);
                a2 = fma2(v1.x, TT[2 * t + 2], a2);
                a3 = fma2(v1.y, TT[2 * t + 3], a3);
            }
            part[lb][p][q] = add2(add2(a0, a1), add2(a2, a3));
        }
        __syncthreads();   // BAR2: partials visible; est_dup reads done

        {
            ulonglong2 pr = *reinterpret_cast<const ulonglong2*>(&part[lb][p][0]);
            pred2 = add2(pr.x, pr.y);
        }

        if (q == 1) {
            float px, py; unpack2(pred2, px, py);
            po[k * Sn + p]      = px;     // pred output
            po[k * Sn + p + 32] = py;
        }

        l0 = n0; l1 = n1;
    }
}

extern "C" void kernel_launch(void* const* d_in, const int* in_sizes, int n_in,
                              void* d_out, int out_size) {
    const float* lik    = (const float*)d_in[0];   // [256, 2048, 64]
    const float* init_s = (const float*)d_in[1];   // [64]
    const float* Tm     = (const float*)d_in[2];   // [64, 64]
    float* eo = (float*)d_out;                      // est_traj first
    float* po = eo + (size_t)Bn * Hn * Sn;          // pred_traj second

    hmm_forward_kernel<<<Bn / 2, 128>>>(lik, init_s, Tm, eo, po);
}

// round 3
// speedup vs baseline: 2.2162x; 2.2162x over previous
#include <cuda_runtime.h>
#include <cstdint>

// HMM forward filter, one warp per batch.
//   w = pred ∘ lik ; s = Σ|w| ; est = w/s ; pred' = (w @ T)/s
// Scale-deferred: the reduction (shfl butterfly + rcp) overlaps the matvec;
// only one f32x2 multiply by {r,r} stays on the recurrence chain.
// Lane p owns states (2p, 2p+1). T columns live in registers as packed
// {T[j][2p], T[j][2p+1]} (64 x u64). u is exchanged via a 512B shared buffer
// of duplicated pairs {u,u} so the matvec is LDS.128(broadcast)+fma.rn.f32x2.
// lik is prefetched 4 steps ahead through a register FIFO (unroll-by-4).

#define Bn 256
#define Hn 2048
#define Sn 64
#define HMM_EPS 1e-12f
#define UD 4              // unroll / prefetch depth

using u64 = unsigned long long;

__device__ __forceinline__ u64 fma2(u64 a, u64 b, u64 c) {
    u64 d; asm("fma.rn.f32x2 %0, %1, %2, %3;" : "=l"(d) : "l"(a), "l"(b), "l"(c)); return d;
}
__device__ __forceinline__ u64 mul2(u64 a, u64 b) {
    u64 d; asm("mul.rn.f32x2 %0, %1, %2;" : "=l"(d) : "l"(a), "l"(b)); return d;
}
__device__ __forceinline__ u64 add2(u64 a, u64 b) {
    u64 d; asm("add.rn.f32x2 %0, %1, %2;" : "=l"(d) : "l"(a), "l"(b)); return d;
}
__device__ __forceinline__ u64 pack2(float lo, float hi) {
    u64 d; asm("mov.b64 %0, {%1, %2};" : "=l"(d) : "f"(lo), "f"(hi)); return d;
}
__device__ __forceinline__ void unpack2(u64 a, float& x, float& y) {
    asm("mov.b64 {%0, %1}, %2;" : "=f"(x), "=f"(y) : "l"(a));
}
__device__ __forceinline__ float fast_rcp(float s) {
    float r; asm("rcp.approx.f32 %0, %1;" : "=f"(r) : "f"(s)); return r;
}

__global__ void __launch_bounds__(64, 1) hmm_forward_kernel(
    const float* __restrict__ lik,    // [B, H, S]
    const float* __restrict__ init_s, // [S]
    const float* __restrict__ Tm,     // [S, S] row-major
    float* __restrict__ est_out,      // [B, H, S]
    float* __restrict__ pred_out)     // [B, H, S]
{
    __shared__ alignas(16) u64 udup[2][2][Sn];   // [warp][buf][state], {u,u} pairs

    const int p  = threadIdx.x & 31;
    const int lb = threadIdx.x >> 5;
    const int b  = blockIdx.x * 2 + lb;

    // T columns, packed per lane: TT[j] = {T[j][2p], T[j][2p+1]}  (contiguous 8B load)
    u64 TT[Sn];
#pragma unroll
    for (int j = 0; j < Sn; j++)
        TT[j] = *reinterpret_cast<const u64*>(Tm + j * Sn + 2 * p);

    const float* likp = lik + (size_t)b * Hn * Sn + 2 * p;
    float* eo = est_out  + (size_t)b * Hn * Sn + 2 * p;
    float* po = pred_out + (size_t)b * Hn * Sn + 2 * p;

    // ---- pred0 = init @ T (stage init into buf 1) ----
    {
        float a0 = init_s[2 * p], a1 = init_s[2 * p + 1];
        float4 f; f.x = a0; f.y = a0; f.z = a1; f.w = a1;
        *reinterpret_cast<float4*>(&udup[lb][1][2 * p]) = f;
    }
    __syncwarp();
    u64 pred2;
    {
        const ulonglong2* uv = reinterpret_cast<const ulonglong2*>(udup[lb][1]);
        u64 a0 = 0, a1 = 0, a2 = 0, a3 = 0;
#pragma unroll
        for (int t = 0; t < 32; t += 2) {
            ulonglong2 v0 = uv[t];
            ulonglong2 v1 = uv[t + 1];
            a0 = fma2(v0.x, TT[2 * t + 0], a0);
            a1 = fma2(v0.y, TT[2 * t + 1], a1);
            a2 = fma2(v1.x, TT[2 * t + 2], a2);
            a3 = fma2(v1.y, TT[2 * t + 3], a3);
        }
        pred2 = add2(add2(a0, a1), add2(a2, a3));
    }

    // ---- lik register FIFO (UD steps deep) ----
    u64 fifo[UD];
#pragma unroll
    for (int j = 0; j < UD; j++)
        fifo[j] = *reinterpret_cast<const u64*>(likp + (size_t)j * Sn);

    // ---- main recurrence ----
    for (int kk = 0; kk < Hn; kk += UD) {
#pragma unroll
        for (int j = 0; j < UD; j++) {
            const int k = kk + j;
            const u64 lk = fifo[j];
            int kn = k + UD; if (kn > Hn - 1) kn = Hn - 1;
            fifo[j] = *reinterpret_cast<const u64*>(likp + (size_t)kn * Sn);

            // u = pred ∘ lik
            const u64 u2 = mul2(pred2, lk);
            float ux, uy; unpack2(u2, ux, uy);

            // exchange u as duplicated pairs (one STS.128 per lane)
            u64* ub = udup[lb][k & 1];
            { float4 f; f.x = ux; f.y = ux; f.z = uy; f.w = uy;
              *reinterpret_cast<float4*>(&ub[2 * p]) = f; }
            __syncwarp();

            // L1 reduction — independent of the matvec below; compiler
            // interleaves the shfl chain with the LDS/FMA stream.
            float s = fabsf(ux) + fabsf(uy);
#pragma unroll
            for (int o = 16; o; o >>= 1) s += __shfl_xor_sync(0xFFFFFFFFu, s, o);
            const float r = fast_rcp(fmaxf(s, HMM_EPS));

            // matvec: acc_i = Σ_j u_j * T[j][i]  (unnormalized)
            u64 a0 = 0, a1 = 0, a2 = 0, a3 = 0;
            const ulonglong2* uv = reinterpret_cast<const ulonglong2*>(ub);
#pragma unroll
            for (int t = 0; t < 32; t += 2) {
                ulonglong2 v0 = uv[t];
                ulonglong2 v1 = uv[t + 1];
                a0 = fma2(v0.x, TT[2 * t + 0], a0);
                a1 = fma2(v0.y, TT[2 * t + 1], a1);
                a2 = fma2(v1.x, TT[2 * t + 2], a2);
                a3 = fma2(v1.y, TT[2 * t + 3], a3);
            }
            const u64 rr  = pack2(r, r);
            const u64 sum = add2(add2(a0, a1), add2(a2, a3));

            const u64 e2 = mul2(u2, rr);          // est output
            pred2 = mul2(sum, rr);                // pred' = (u@T)·r = est@T

            *reinterpret_cast<u64*>(eo + (size_t)k * Sn) = e2;
            *reinterpret_cast<u64*>(po + (size_t)k * Sn) = pred2;
        }
    }
}

extern "C" void kernel_launch(void* const* d_in, const int* in_sizes, int n_in,
                              void* d_out, int out_size) {
    const float* lik    = (const float*)d_in[0];   // [256, 2048, 64]
    const float* init_s = (const float*)d_in[1];   // [64]
    const float* Tm     = (const float*)d_in[2];   // [64, 64]
    float* eo = (float*)d_out;                      // est_traj first
    float* po = eo + (size_t)Bn * Hn * Sn;          // pred_traj second

    hmm_forward_kernel<<<Bn / 2, 64>>>(lik, init_s, Tm, eo, po);
}

// round 4
// speedup vs baseline: 2.5926x; 1.1698x over previous
#include <cuda_runtime.h>
#include <cstdint>

// HMM forward filter, one warp per batch, normalization OFF the recurrence.
// Since T is row-stochastic, sum(t@T) = sum(t), so we carry the UNNORMALIZED
// vector v:
//   t  = v ∘ lik_k              (4-cyc mul2 — chain head)
//   v' = t @ T                  (smem exchange + fma2 chain — the whole chain)
//   s  = Σ t ; r = 1/s          (shfl butterfly + rcp — shadow, outputs only)
//   est_out = t·r ; pred_out = v'·r
//   v  = v' · 2^(127-exp(s))    (exact pow2 rescale, keeps fp32 in range)
// Lane p owns states (2p,2p+1); T columns in regs as {T[j][2p],T[j][2p+1]};
// t exchanged as duplicated pairs {t,t} -> matvec = LDS.128(bcast)+fma.rn.f32x2.
// lik prefetched through an 8-deep register FIFO.

#define Bn 256
#define Hn 2048
#define Sn 64
#define UD 8              // unroll / prefetch depth

using u64 = unsigned long long;

__device__ __forceinline__ u64 fma2(u64 a, u64 b, u64 c) {
    u64 d; asm("fma.rn.f32x2 %0, %1, %2, %3;" : "=l"(d) : "l"(a), "l"(b), "l"(c)); return d;
}
__device__ __forceinline__ u64 mul2(u64 a, u64 b) {
    u64 d; asm("mul.rn.f32x2 %0, %1, %2;" : "=l"(d) : "l"(a), "l"(b)); return d;
}
__device__ __forceinline__ u64 add2(u64 a, u64 b) {
    u64 d; asm("add.rn.f32x2 %0, %1, %2;" : "=l"(d) : "l"(a), "l"(b)); return d;
}
__device__ __forceinline__ u64 pack2(float lo, float hi) {
    u64 d; asm("mov.b64 %0, {%1, %2};" : "=l"(d) : "f"(lo), "f"(hi)); return d;
}
__device__ __forceinline__ void unpack2(u64 a, float& x, float& y) {
    asm("mov.b64 {%0, %1}, %2;" : "=f"(x), "=f"(y) : "l"(a));
}
__device__ __forceinline__ float fast_rcp(float s) {
    float r; asm("rcp.approx.f32 %0, %1;" : "=f"(r) : "f"(s)); return r;
}

__global__ void __launch_bounds__(64, 1) hmm_forward_kernel(
    const float* __restrict__ lik,    // [B, H, S]
    const float* __restrict__ init_s, // [S]
    const float* __restrict__ Tm,     // [S, S] row-major
    float* __restrict__ est_out,      // [B, H, S]
    float* __restrict__ pred_out)     // [B, H, S]
{
    __shared__ alignas(16) u64 tdup[2][2][Sn];   // [warp][parity][state] = {t,t}

    const int p  = threadIdx.x & 31;
    const int lb = threadIdx.x >> 5;
    const int b  = blockIdx.x * 2 + lb;

    // T columns packed per lane: TT[j] = {T[j][2p], T[j][2p+1]}
    u64 TT[Sn];
#pragma unroll
    for (int j = 0; j < Sn; j++)
        TT[j] = *reinterpret_cast<const u64*>(Tm + j * Sn + 2 * p);

    const float* likp = lik + (size_t)b * Hn * Sn + 2 * p;
    float* eo = est_out  + (size_t)b * Hn * Sn + 2 * p;
    float* po = pred_out + (size_t)b * Hn * Sn + 2 * p;

    // ---- v = pred0 = init @ T ----
    {
        float a0 = init_s[2 * p], a1 = init_s[2 * p + 1];
        float4 f; f.x = a0; f.y = a0; f.z = a1; f.w = a1;
        *reinterpret_cast<float4*>(&tdup[lb][1][2 * p]) = f;
    }
    __syncwarp();
    u64 v2;
    {
        const ulonglong2* uv = reinterpret_cast<const ulonglong2*>(tdup[lb][1]);
        u64 a0 = 0, a1 = 0, a2 = 0, a3 = 0;
#pragma unroll
        for (int t = 0; t < 32; t += 2) {
            ulonglong2 w0 = uv[t];
            ulonglong2 w1 = uv[t + 1];
            a0 = fma2(w0.x, TT[2 * t + 0], a0);
            a1 = fma2(w0.y, TT[2 * t + 1], a1);
            a2 = fma2(w1.x, TT[2 * t + 2], a2);
            a3 = fma2(w1.y, TT[2 * t + 3], a3);
        }
        v2 = add2(add2(a0, a1), add2(a2, a3));
    }
    __syncwarp();

    // ---- lik register FIFO ----
    u64 fifo[UD];
#pragma unroll
    for (int j = 0; j < UD; j++)
        fifo[j] = *reinterpret_cast<const u64*>(likp + (size_t)j * Sn);

    // ---- main recurrence ----
    for (int kk = 0; kk < Hn; kk += UD) {
#pragma unroll
        for (int j = 0; j < UD; j++) {
            const int k = kk + j;
            const u64 lk = fifo[j];
            int kn = k + UD; if (kn > Hn - 1) kn = Hn - 1;
            fifo[j] = *reinterpret_cast<const u64*>(likp + (size_t)kn * Sn);

            // ---- chain: t = v ∘ lik, exchange as dup pairs ----
            const u64 t2 = mul2(v2, lk);
            float tx, ty; unpack2(t2, tx, ty);
            u64* tb = tdup[lb][k & 1];
            { float4 f; f.x = tx; f.y = tx; f.z = ty; f.w = ty;
              *reinterpret_cast<float4*>(&tb[2 * p]) = f; }
            __syncwarp();

            // ---- shadow: s = Σt, r = 1/s, pow2 rescale factor ----
            float s = fabsf(tx) + fabsf(ty);
#pragma unroll
            for (int o = 16; o; o >>= 1) s += __shfl_xor_sync(0xFFFFFFFFu, s, o);
            s = fmaxf(s, 1e-35f);
            const float r = fast_rcp(s);
            const unsigned eb = (__float_as_uint(s) >> 23) & 0xFFu;
            const float f = __uint_as_float((254u - eb) << 23);   // exact 2^(127-e)

            // ---- chain: v' = t @ T ----
            u64 a0 = 0, a1 = 0, a2 = 0, a3 = 0;
            const ulonglong2* uv = reinterpret_cast<const ulonglong2*>(tb);
#pragma unroll
            for (int t = 0; t < 32; t += 2) {
                ulonglong2 w0 = uv[t];
                ulonglong2 w1 = uv[t + 1];
                a0 = fma2(w0.x, TT[2 * t + 0], a0);
                a1 = fma2(w0.y, TT[2 * t + 1], a1);
                a2 = fma2(w1.x, TT[2 * t + 2], a2);
                a3 = fma2(w1.y, TT[2 * t + 3], a3);
            }
            const u64 sum = add2(add2(a0, a1), add2(a2, a3));

            // chain tail: exact pow2 rescale keeps magnitudes in range
            v2 = mul2(sum, pack2(f, f));

            // ---- shadow: normalized outputs ----
            const u64 rr = pack2(r, r);
            *reinterpret_cast<u64*>(eo + (size_t)k * Sn) = mul2(t2, rr);
            *reinterpret_cast<u64*>(po + (size_t)k * Sn) = mul2(sum, rr);
        }
    }
}

extern "C" void kernel_launch(void* const* d_in, const int* in_sizes, int n_in,
                              void* d_out, int out_size) {
    const float* lik    = (const float*)d_in[0];   // [256, 2048, 64]
    const float* init_s = (const float*)d_in[1];   // [64]
    const float* Tm     = (const float*)d_in[2];   // [64, 64]
    float* eo = (float*)d_out;                      // est_traj first
    float* po = eo + (size_t)Bn * Hn * Sn;          // pred_traj second

    hmm_forward_kernel<<<Bn / 2, 64>>>(lik, init_s, Tm, eo, po);
}